// round 14
// baseline (speedup 1.0000x reference)
#include <cuda_runtime.h>
#include <cuda_fp16.h>
#include <stdint.h>
#include <cstdint>
#include <math.h>

// ---------------------------------------------------------------------------
// Problem constants
// ---------------------------------------------------------------------------
#define B_      8
#define DIM_    512
#define IMG_    32
#define HEADS_  8
#define DH_     64
#define N_      1024
#define INNER_  512
#define MTOT    (B_ * N_)                 // 8192
#define PROJ    ((long)MTOT * DIM_)       // 4,194,304

// ---------------------------------------------------------------------------
// Device scratch (fp16 intermediates)
// ---------------------------------------------------------------------------
__device__ __align__(256) __half g_y[3ll * MTOT * DIM_];     // dwconv+BN out
__device__ __align__(256) __half g_qkv[3ll * MTOT * DIM_];   // pointwise out
__device__ __align__(256) __half g_att[(long)MTOT * INNER_]; // attention out
__device__ __align__(256) __half g_pw[3 * INNER_ * DIM_];    // fp16 weights
__device__ __align__(256) __half g_ow[DIM_ * INNER_];

// ---------------------------------------------------------------------------
// mma / ldmatrix / cp.async helpers
// ---------------------------------------------------------------------------
__device__ __forceinline__ unsigned smem_u32(const void* p) {
    return (unsigned)__cvta_generic_to_shared(p);
}
__device__ __forceinline__ void ldm4(unsigned& r0, unsigned& r1,
                                     unsigned& r2, unsigned& r3, unsigned a) {
    asm volatile("ldmatrix.sync.aligned.m8n8.x4.shared.b16 {%0,%1,%2,%3}, [%4];"
                 : "=r"(r0), "=r"(r1), "=r"(r2), "=r"(r3) : "r"(a));
}
__device__ __forceinline__ void ldm4t(unsigned& r0, unsigned& r1,
                                      unsigned& r2, unsigned& r3, unsigned a) {
    asm volatile("ldmatrix.sync.aligned.m8n8.x4.trans.shared.b16 {%0,%1,%2,%3}, [%4];"
                 : "=r"(r0), "=r"(r1), "=r"(r2), "=r"(r3) : "r"(a));
}
__device__ __forceinline__ void mma16816(float* c, const unsigned* a,
                                         const unsigned* b) {
    asm volatile(
        "mma.sync.aligned.m16n8k16.row.col.f32.f16.f16.f32 "
        "{%0,%1,%2,%3}, {%4,%5,%6,%7}, {%8,%9}, {%0,%1,%2,%3};"
        : "+f"(c[0]), "+f"(c[1]), "+f"(c[2]), "+f"(c[3])
        : "r"(a[0]), "r"(a[1]), "r"(a[2]), "r"(a[3]), "r"(b[0]), "r"(b[1]));
}
__device__ __forceinline__ unsigned pack_h2(float a, float b) {
    __half2 h = __floats2half2_rn(a, b);   // low = a
    return *reinterpret_cast<unsigned*>(&h);
}
__device__ __forceinline__ unsigned hex2(unsigned x) {   // exp2 on fp16x2
    unsigned r;
    asm("ex2.approx.f16x2 %0, %1;" : "=r"(r) : "r"(x));
    return r;
}
__device__ __forceinline__ void cp16(unsigned dst, const void* src) {
    asm volatile("cp.async.ca.shared.global [%0], [%1], 16;"
                 :: "r"(dst), "l"(src));
}
#define CP_COMMIT()  asm volatile("cp.async.commit_group;")
#define CP_WAIT1()   asm volatile("cp.async.wait_group 1;")
#define CP_WAIT0()   asm volatile("cp.async.wait_group 0;")

// ---------------------------------------------------------------------------
// Kernel 0: weight conversion fp32 -> fp16
// ---------------------------------------------------------------------------
__global__ void wcvt_kernel(const float* __restrict__ pw,
                            const float* __restrict__ ow)
{
    const int i = blockIdx.x * blockDim.x + threadIdx.x;   // 0..262143
#pragma unroll
    for (int j = 0; j < 3; j++)
        g_pw[j * 262144 + i] = __float2half_rn(pw[j * 262144 + i]);
    g_ow[i] = __float2half_rn(ow[i]);
}

// ---------------------------------------------------------------------------
// Kernel 1: fused depthwise 3x3 conv + folded eval-BN (q,k,v), fp16 out
// ---------------------------------------------------------------------------
__global__ void __launch_bounds__(512) dwconv_bn_kernel(
    const float* __restrict__ x,
    const float* __restrict__ dw_w, const float* __restrict__ dw_b,
    const float* __restrict__ bn_g, const float* __restrict__ bn_b,
    const float* __restrict__ bn_m, const float* __restrict__ bn_v)
{
    const int c = threadIdx.x;
    const int l = blockIdx.x;
    const int b = blockIdx.y;

    float wgt[3][9], sc[3], bi[3];
#pragma unroll
    for (int i = 0; i < 3; i++) {
        const int wb = (i * DIM_ + c) * 9;
#pragma unroll
        for (int k = 0; k < 9; k++) wgt[i][k] = dw_w[wb + k];
        const float s = bn_g[i * DIM_ + c] * rsqrtf(bn_v[i * DIM_ + c] + 1e-5f);
        sc[i] = s;
        bi[i] = (dw_b[i * DIM_ + c] - bn_m[i * DIM_ + c]) * s + bn_b[i * DIM_ + c];
    }

    const float* xb = x + (long)b * N_ * DIM_ + c;
    const bool rv[3]  = { l - 1 >= 0, true, l + 1 < IMG_ };
    const int  rof[3] = { (l - 1) * IMG_, l * IMG_, (l + 1) * IMG_ };

    float c0[3], c1[3], c2[3];
#pragma unroll
    for (int r = 0; r < 3; r++) {
        c0[r] = 0.f;
        c1[r] = rv[r] ? xb[(long)(rof[r]) * DIM_] : 0.f;
    }

    for (int w = 0; w < IMG_; w++) {
#pragma unroll
        for (int r = 0; r < 3; r++)
            c2[r] = (rv[r] && (w + 1) < IMG_) ? xb[(long)(rof[r] + w + 1) * DIM_] : 0.f;

        const long oidx = ((long)b * N_ + l * IMG_ + w) * DIM_ + c;
#pragma unroll
        for (int i = 0; i < 3; i++) {
            float a =
                c0[0]*wgt[i][0] + c1[0]*wgt[i][1] + c2[0]*wgt[i][2] +
                c0[1]*wgt[i][3] + c1[1]*wgt[i][4] + c2[1]*wgt[i][5] +
                c0[2]*wgt[i][6] + c1[2]*wgt[i][7] + c2[2]*wgt[i][8];
            g_y[(long)i * PROJ + oidx] = __float2half_rn(a * sc[i] + bi[i]);
        }
#pragma unroll
        for (int r = 0; r < 3; r++) { c0[r] = c1[r]; c1[r] = c2[r]; }
    }
}

// ---------------------------------------------------------------------------
// Kernel 2/4: fp16 NT GEMM via HMMA, 3-stage cp.async, 1 sync/iter.
// Block 128x128xK32, 256 threads = 8 warps (4x2), warp tile 32x64.
// (verified; unchanged this round)
// ---------------------------------------------------------------------------
#define GEMM_SMEM 61440
#define ASD(s, r, c) smd[(s) * 5120 + (r) * 40 + (c)]
#define BSD(s, r, c) smd[15360 + (s) * 5120 + (r) * 40 + (c)]

template <bool HALF_OUT>
__global__ void __launch_bounds__(256, 2) gemm_h_kernel(
    const __half* __restrict__ Ag, const __half* __restrict__ Wg,
    const float* __restrict__ biasg, void* __restrict__ Cg,
    long sA, long sW, long sBias, long sC)
{
    extern __shared__ __half smd[];

    const int z = blockIdx.z;
    const __half* A    = Ag + (long)z * sA;
    const __half* W    = Wg + (long)z * sW;
    const float*  bias = biasg + (long)z * sBias;

    const int tid  = threadIdx.x;
    const int lane = tid & 31;
    const int warp = tid >> 5;
    const int wm   = warp >> 1;
    const int wn   = warp & 1;
    const int bm   = blockIdx.y * 128;
    const int bn   = blockIdx.x * 128;

    const int crow = tid >> 1;            // 0..127
    const int ccol = (tid & 1) * 16;      // 0 / 16
    const __half* Aptr = A + (long)(bm + crow) * 512 + ccol;
    const __half* Wptr = W + (long)(bn + crow) * 512 + ccol;

    float acc[2][8][4];
#pragma unroll
    for (int mt = 0; mt < 2; mt++)
#pragma unroll
        for (int nt = 0; nt < 8; nt++)
#pragma unroll
            for (int j = 0; j < 4; j++) acc[mt][nt][j] = 0.f;

#pragma unroll
    for (int p = 0; p < 2; p++) {
        const long ko = (long)p * 32;
        cp16(smem_u32(&ASD(p, crow, ccol)),     Aptr + ko);
        cp16(smem_u32(&ASD(p, crow, ccol + 8)), Aptr + ko + 8);
        cp16(smem_u32(&BSD(p, crow, ccol)),     Wptr + ko);
        cp16(smem_u32(&BSD(p, crow, ccol + 8)), Wptr + ko + 8);
        CP_COMMIT();
    }

    const int aRow    = (lane & 15);
    const int aColSel = (lane >> 4) * 8;
    const int bRow    = (lane & 7) + (lane >> 4) * 8;
    const int bColSel = ((lane >> 3) & 1) * 8;

#pragma unroll 1
    for (int it = 0; it < 16; it++) {
        const int s = it % 3;
        if (it < 15) CP_WAIT1(); else CP_WAIT0();
        __syncthreads();
        if (it + 2 < 16) {
            const int ns = (it + 2) % 3;
            const long ko = (long)(it + 2) * 32;
            cp16(smem_u32(&ASD(ns, crow, ccol)),     Aptr + ko);
            cp16(smem_u32(&ASD(ns, crow, ccol + 8)), Aptr + ko + 8);
            cp16(smem_u32(&BSD(ns, crow, ccol)),     Wptr + ko);
            cp16(smem_u32(&BSD(ns, crow, ccol + 8)), Wptr + ko + 8);
            CP_COMMIT();
        }

#pragma unroll
        for (int ks = 0; ks < 2; ks++) {
            const int kk = ks * 16;
            unsigned af[2][4];
#pragma unroll
            for (int mt = 0; mt < 2; mt++) {
                unsigned addr = smem_u32(&ASD(s, wm * 32 + mt * 16 + aRow, kk + aColSel));
                ldm4(af[mt][0], af[mt][1], af[mt][2], af[mt][3], addr);
            }
            unsigned bf[8][2];
#pragma unroll
            for (int np = 0; np < 4; np++) {
                unsigned addr = smem_u32(&BSD(s, wn * 64 + np * 16 + bRow, kk + bColSel));
                unsigned r0, r1, r2, r3;
                ldm4(r0, r1, r2, r3, addr);
                bf[np * 2][0] = r0;     bf[np * 2][1] = r1;
                bf[np * 2 + 1][0] = r2; bf[np * 2 + 1][1] = r3;
            }
#pragma unroll
            for (int mt = 0; mt < 2; mt++)
#pragma unroll
                for (int nt = 0; nt < 8; nt++)
                    mma16816(acc[mt][nt], af[mt], bf[nt]);
        }
    }

    const int rq = lane >> 2;
    const int cq = (lane & 3) * 2;
#pragma unroll
    for (int mt = 0; mt < 2; mt++) {
        const int row0 = bm + wm * 32 + mt * 16 + rq;
#pragma unroll
        for (int nt = 0; nt < 8; nt++) {
            const int col = bn + wn * 64 + nt * 8 + cq;
            const float b0 = bias[col], b1 = bias[col + 1];
            if (HALF_OUT) {
                __half* C = (__half*)Cg + (long)z * sC;
                *(__half2*)(C + (long)row0 * 512 + col) =
                    __floats2half2_rn(acc[mt][nt][0] + b0, acc[mt][nt][1] + b1);
                *(__half2*)(C + (long)(row0 + 8) * 512 + col) =
                    __floats2half2_rn(acc[mt][nt][2] + b0, acc[mt][nt][3] + b1);
            } else {
                float* C = (float*)Cg + (long)z * sC;
                *(float2*)(C + (long)row0 * 512 + col) =
                    make_float2(acc[mt][nt][0] + b0, acc[mt][nt][1] + b1);
                *(float2*)(C + (long)(row0 + 8) * 512 + col) =
                    make_float2(acc[mt][nt][2] + b0, acc[mt][nt][3] + b1);
            }
        }
    }
}

// ---------------------------------------------------------------------------
// Kernel 3: flash attention v6 — m32 warp tile (smem:tensor rebalance).
// Evidence: tensor pipe and smem crossbar were co-saturated ~1:1 (every warp
// redundantly ldmatrix-loads the same K/V frags, amortized over only 16 q
// rows). Now each warp owns 32 q rows: every K/V fragment feeds 2 MMAs, so
// smem bytes per MMA halve (ratio -> 2:1). Block = 128 threads (4 warps),
// q-tile 128, grid unchanged, 2 blocks/SM kept (regs/smem fit).
// Max-free softmax, fp16x2 exp2, row sums via MMA vs ones, 3-stage cp.async.
// Dynamic smem: Q 128x72 + 3 stages x (K 64x72 + V 64x72) = 73728 B.
// ---------------------------------------------------------------------------
#define ATT_SMEM 73728
#define QS(r, c)     sm[(r) * 72 + (c)]
#define KS(s, r, c)  sm[9216  + (s) * 4608 + (r) * 72 + (c)]
#define VS(s, r, c)  sm[23040 + (s) * 4608 + (r) * 72 + (c)]

__global__ void __launch_bounds__(128, 2) attn_h_kernel(
    const __half* __restrict__ qkv, __half* __restrict__ attout)
{
    extern __shared__ __half sm[];

    const int tid  = threadIdx.x;
    const int lane = tid & 31;
    const int warp = tid >> 5;           // 0..3
    const int qt = blockIdx.x, h = blockIdx.y, b = blockIdx.z;

    const __half* Qg = qkv +            ((long)b * N_ + qt * 128) * 512 + h * 64;
    const __half* Kg = qkv + PROJ     + (long)b * N_ * 512 + h * 64;
    const __half* Vg = qkv + 2 * PROJ + (long)b * N_ * 512 + h * 64;

    // ---- kick off K/V tiles 0,1 via cp.async (128 threads, 4 chunks each) ----
#pragma unroll
    for (int p = 0; p < 2; p++) {
#pragma unroll
        for (int c = 0; c < 4; c++) {
            const int idx = tid + 128 * c;          // 0..511
            const int row = idx >> 3;               // 0..63
            const int col = (idx & 7) * 8;          // 0..56
            cp16(smem_u32(&KS(p, row, col)), Kg + (long)(p * 64 + row) * 512 + col);
            cp16(smem_u32(&VS(p, row, col)), Vg + (long)(p * 64 + row) * 512 + col);
        }
        CP_COMMIT();
    }

    // ---- load Q tile scaled by 0.125 * log2(e) ----
    {
        const __half2 s2 = __float2half2_rn(0.125f * 1.4426950408889634f);
#pragma unroll
        for (int p = 0; p < 8; p++) {
            const int idx = tid + 128 * p;          // 0..1023
            const int r   = idx >> 3;               // 0..127
            const int col = (idx & 7) * 8;
            uint4 v = *(const uint4*)(Qg + (long)r * 512 + col);
            __half2* hv = (__half2*)&v;
#pragma unroll
            for (int i = 0; i < 4; i++) hv[i] = __hmul2(hv[i], s2);
            *(uint4*)&QS(r, col) = v;
        }
    }
    __syncthreads();

    // ---- Q fragments for two m16 tiles (rows warp*32 and warp*32+16) ----
    unsigned qfA[4][4], qfB[4][4];
    {
        const int rA = warp * 32 + (lane >> 2);
        const int rB = rA + 16;
#pragma unroll
        for (int ks = 0; ks < 4; ks++) {
            const int d = ks * 16 + (lane & 3) * 2;
            qfA[ks][0] = *(const unsigned*)&QS(rA, d);
            qfA[ks][1] = *(const unsigned*)&QS(rA + 8, d);
            qfA[ks][2] = *(const unsigned*)&QS(rA, d + 8);
            qfA[ks][3] = *(const unsigned*)&QS(rA + 8, d + 8);
            qfB[ks][0] = *(const unsigned*)&QS(rB, d);
            qfB[ks][1] = *(const unsigned*)&QS(rB + 8, d);
            qfB[ks][2] = *(const unsigned*)&QS(rB, d + 8);
            qfB[ks][3] = *(const unsigned*)&QS(rB + 8, d + 8);
        }
    }

    float oA[8][4], oB[8][4];
#pragma unroll
    for (int nt = 0; nt < 8; nt++)
#pragma unroll
        for (int j = 0; j < 4; j++) { oA[nt][j] = 0.f; oB[nt][j] = 0.f; }
    float rsA[4] = {0.f, 0.f, 0.f, 0.f};
    float rsB[4] = {0.f, 0.f, 0.f, 0.f};
    const unsigned ONES2 = 0x3C003C00u;            // (1.0h, 1.0h)
    const unsigned bones[2] = { ONES2, ONES2 };

    const int bRow = (lane & 7) + (lane >> 4) * 8;
    const int bColSel = ((lane >> 3) & 1) * 8;
    const int vRow = ((lane >> 3) & 1) * 8 + (lane & 7);
    const int vCol = (lane >> 4) * 8;

    for (int kt = 0; kt < 16; kt++) {
        const int s = kt % 3;
        if (kt < 15) CP_WAIT1(); else CP_WAIT0();
        __syncthreads();
        if (kt + 2 < 16) {                         // fill stage (kt+2)%3
            const int nk = kt + 2, ns = nk % 3;
#pragma unroll
            for (int c = 0; c < 4; c++) {
                const int idx = tid + 128 * c;
                const int row = idx >> 3;
                const int col = (idx & 7) * 8;
                cp16(smem_u32(&KS(ns, row, col)),
                     Kg + (long)(nk * 64 + row) * 512 + col);
                cp16(smem_u32(&VS(ns, row, col)),
                     Vg + (long)(nk * 64 + row) * 512 + col);
            }
            CP_COMMIT();
        }

        // ---- 4 key-chunks of 16: S -> exp2 -> rowsum + PV (two m-tiles) ----
#pragma unroll
        for (int t = 0; t < 4; t++) {
            float s0A[4] = {0.f, 0.f, 0.f, 0.f};
            float s1A[4] = {0.f, 0.f, 0.f, 0.f};
            float s0B[4] = {0.f, 0.f, 0.f, 0.f};
            float s1B[4] = {0.f, 0.f, 0.f, 0.f};
#pragma unroll
            for (int ks = 0; ks < 4; ks++) {
                unsigned r0, r1, r2, r3;
                ldm4(r0, r1, r2, r3,
                     smem_u32(&KS(s, t * 16 + bRow, ks * 16 + bColSel)));
                unsigned kb0[2] = { r0, r1 };
                unsigned kb1[2] = { r2, r3 };
                mma16816(s0A, qfA[ks], kb0);
                mma16816(s1A, qfA[ks], kb1);
                mma16816(s0B, qfB[ks], kb0);
                mma16816(s1B, qfB[ks], kb1);
            }

            unsigned paA[4], paB[4];
            paA[0] = hex2(pack_h2(s0A[0], s0A[1]));
            paA[1] = hex2(pack_h2(s0A[2], s0A[3]));
            paA[2] = hex2(pack_h2(s1A[0], s1A[1]));
            paA[3] = hex2(pack_h2(s1A[2], s1A[3]));
            paB[0] = hex2(pack_h2(s0B[0], s0B[1]));
            paB[1] = hex2(pack_h2(s0B[2], s0B[3]));
            paB[2] = hex2(pack_h2(s1B[0], s1B[1]));
            paB[3] = hex2(pack_h2(s1B[2], s1B[3]));

            mma16816(rsA, paA, bones);
            mma16816(rsB, paB, bones);

#pragma unroll
            for (int dg = 0; dg < 4; dg++) {
                unsigned r0, r1, r2, r3;
                ldm4t(r0, r1, r2, r3,
                      smem_u32(&VS(s, t * 16 + vRow, dg * 16 + vCol)));
                unsigned bf0[2] = { r0, r1 };
                unsigned bf1[2] = { r2, r3 };
                mma16816(oA[dg * 2],     paA, bf0);
                mma16816(oA[dg * 2 + 1], paA, bf1);
                mma16816(oB[dg * 2],     paB, bf0);
                mma16816(oB[dg * 2 + 1], paB, bf1);
            }
        }
    }

    // ---- normalize & store (fp16) ----
    const float invaA = 1.f / rsA[0], invbA = 1.f / rsA[2];
    const float invaB = 1.f / rsB[0], invbB = 1.f / rsB[2];
    const int rA = warp * 32 + (lane >> 2);
    const long row0 = (long)b * N_ + qt * 128 + rA;
#pragma unroll
    for (int nt = 0; nt < 8; nt++) {
        const int col = h * 64 + nt * 8 + (lane & 3) * 2;
        *(__half2*)(attout + row0 * 512 + col) =
            __floats2half2_rn(oA[nt][0] * invaA, oA[nt][1] * invaA);
        *(__half2*)(attout + (row0 + 8) * 512 + col) =
            __floats2half2_rn(oA[nt][2] * invbA, oA[nt][3] * invbA);
        *(__half2*)(attout + (row0 + 16) * 512 + col) =
            __floats2half2_rn(oB[nt][0] * invaB, oB[nt][1] * invaB);
        *(__half2*)(attout + (row0 + 24) * 512 + col) =
            __floats2half2_rn(oB[nt][2] * invbB, oB[nt][3] * invbB);
    }
}

// ---------------------------------------------------------------------------
// Host launcher (graph-capturable: kernel launches only)
// ---------------------------------------------------------------------------
extern "C" void kernel_launch(void* const* d_in, const int* in_sizes, int n_in,
                              void* d_out, int out_size)
{
    const float* x     = (const float*)d_in[0];
    const float* dw_w  = (const float*)d_in[1];
    const float* dw_b  = (const float*)d_in[2];
    const float* bn_g  = (const float*)d_in[3];
    const float* bn_b  = (const float*)d_in[4];
    const float* bn_m  = (const float*)d_in[5];
    const float* bn_v  = (const float*)d_in[6];
    const float* pw_w  = (const float*)d_in[7];
    const float* pw_b  = (const float*)d_in[8];
    const float* out_w = (const float*)d_in[9];
    const float* out_b = (const float*)d_in[10];

    __half *yp, *qkvp, *attp, *pwp, *owp;
    cudaGetSymbolAddress((void**)&yp,   g_y);
    cudaGetSymbolAddress((void**)&qkvp, g_qkv);
    cudaGetSymbolAddress((void**)&attp, g_att);
    cudaGetSymbolAddress((void**)&pwp,  g_pw);
    cudaGetSymbolAddress((void**)&owp,  g_ow);

    cudaFuncSetAttribute(attn_h_kernel,
                         cudaFuncAttributeMaxDynamicSharedMemorySize, ATT_SMEM);
    cudaFuncSetAttribute(gemm_h_kernel<true>,
                         cudaFuncAttributeMaxDynamicSharedMemorySize, GEMM_SMEM);
    cudaFuncSetAttribute(gemm_h_kernel<false>,
                         cudaFuncAttributeMaxDynamicSharedMemorySize, GEMM_SMEM);

    // 0) weights -> fp16
    wcvt_kernel<<<1024, 256>>>(pw_w, out_w);

    // 1) depthwise + BN (fp16 out)
    dwconv_bn_kernel<<<dim3(IMG_, B_), DIM_>>>(x, dw_w, dw_b,
                                               bn_g, bn_b, bn_m, bn_v);

    // 2) pointwise 1x1 conv: 3 fp16 GEMMs
    gemm_h_kernel<true><<<dim3(4, 64, 3), 256, GEMM_SMEM>>>(
        yp, pwp, pw_b, (void*)qkvp,
        PROJ, (long)INNER_ * DIM_, (long)INNER_, PROJ);

    // 3) fused flash attention (m32 warp tile, 4 warps/block)
    attn_h_kernel<<<dim3(N_ / 128, HEADS_, B_), 128, ATT_SMEM>>>(qkvp, attp);

    // 4) output projection -> d_out (fp32)
    gemm_h_kernel<false><<<dim3(4, 64, 1), 256, GEMM_SMEM>>>(
        attp, owp, out_b, d_out, 0, 0, 0, 0);
}

// round 17
// speedup vs baseline: 1.7272x; 1.7272x over previous
#include <cuda_runtime.h>
#include <cuda_fp16.h>
#include <stdint.h>
#include <cstdint>
#include <math.h>

// ---------------------------------------------------------------------------
// Problem constants
// ---------------------------------------------------------------------------
#define B_      8
#define DIM_    512
#define IMG_    32
#define HEADS_  8
#define DH_     64
#define N_      1024
#define INNER_  512
#define MTOT    (B_ * N_)                 // 8192
#define PROJ    ((long)MTOT * DIM_)       // 4,194,304

// ---------------------------------------------------------------------------
// Device scratch (fp16 intermediates)
// ---------------------------------------------------------------------------
__device__ __align__(256) __half g_y[3ll * MTOT * DIM_];     // dwconv+BN out
__device__ __align__(256) __half g_qkv[3ll * MTOT * DIM_];   // pointwise out
__device__ __align__(256) __half g_att[(long)MTOT * INNER_]; // attention out
__device__ __align__(256) __half g_pw[3 * INNER_ * DIM_];    // fp16 weights
__device__ __align__(256) __half g_ow[DIM_ * INNER_];

// ---------------------------------------------------------------------------
// mma / ldmatrix / cp.async helpers
// ---------------------------------------------------------------------------
__device__ __forceinline__ unsigned smem_u32(const void* p) {
    return (unsigned)__cvta_generic_to_shared(p);
}
__device__ __forceinline__ void ldm4(unsigned& r0, unsigned& r1,
                                     unsigned& r2, unsigned& r3, unsigned a) {
    asm volatile("ldmatrix.sync.aligned.m8n8.x4.shared.b16 {%0,%1,%2,%3}, [%4];"
                 : "=r"(r0), "=r"(r1), "=r"(r2), "=r"(r3) : "r"(a));
}
__device__ __forceinline__ void ldm4t(unsigned& r0, unsigned& r1,
                                      unsigned& r2, unsigned& r3, unsigned a) {
    asm volatile("ldmatrix.sync.aligned.m8n8.x4.trans.shared.b16 {%0,%1,%2,%3}, [%4];"
                 : "=r"(r0), "=r"(r1), "=r"(r2), "=r"(r3) : "r"(a));
}
__device__ __forceinline__ void mma16816(float* c, const unsigned* a,
                                         const unsigned* b) {
    asm volatile(
        "mma.sync.aligned.m16n8k16.row.col.f32.f16.f16.f32 "
        "{%0,%1,%2,%3}, {%4,%5,%6,%7}, {%8,%9}, {%0,%1,%2,%3};"
        : "+f"(c[0]), "+f"(c[1]), "+f"(c[2]), "+f"(c[3])
        : "r"(a[0]), "r"(a[1]), "r"(a[2]), "r"(a[3]), "r"(b[0]), "r"(b[1]));
}
__device__ __forceinline__ unsigned pack_h2(float a, float b) {
    __half2 h = __floats2half2_rn(a, b);   // low = a
    return *reinterpret_cast<unsigned*>(&h);
}
__device__ __forceinline__ unsigned hex2(unsigned x) {   // exp2 on fp16x2
    unsigned r;
    asm("ex2.approx.f16x2 %0, %1;" : "=r"(r) : "r"(x));
    return r;
}
__device__ __forceinline__ void cp16(unsigned dst, const void* src) {
    asm volatile("cp.async.ca.shared.global [%0], [%1], 16;"
                 :: "r"(dst), "l"(src));
}
#define CP_COMMIT()  asm volatile("cp.async.commit_group;")
#define CP_WAIT1()   asm volatile("cp.async.wait_group 1;")
#define CP_WAIT0()   asm volatile("cp.async.wait_group 0;")

// ---------------------------------------------------------------------------
// Kernel 1: fused depthwise 3x3 conv + folded eval-BN (q,k,v), fp16 out.
// blockIdx.z == 1 blocks instead perform the fp32->fp16 weight conversion
// (independent work, fused into this launch to run concurrently).
// ---------------------------------------------------------------------------
__global__ void __launch_bounds__(512) dwconv_bn_kernel(
    const float* __restrict__ x,
    const float* __restrict__ dw_w, const float* __restrict__ dw_b,
    const float* __restrict__ bn_g, const float* __restrict__ bn_b,
    const float* __restrict__ bn_m, const float* __restrict__ bn_v,
    const float* __restrict__ pw, const float* __restrict__ ow)
{
    if (blockIdx.z == 1) {
        // weight conversion: 256 blocks x 512 thr, 2 elems each of 262144
        const int i0 = (blockIdx.y * IMG_ + blockIdx.x) * 512 + threadIdx.x;
#pragma unroll
        for (int rep = 0; rep < 2; rep++) {
            const int i = i0 + rep * 131072;
#pragma unroll
            for (int j = 0; j < 3; j++)
                g_pw[j * 262144 + i] = __float2half_rn(pw[j * 262144 + i]);
            g_ow[i] = __float2half_rn(ow[i]);
        }
        return;
    }

    const int c = threadIdx.x;
    const int l = blockIdx.x;
    const int b = blockIdx.y;

    float wgt[3][9], sc[3], bi[3];
#pragma unroll
    for (int i = 0; i < 3; i++) {
        const int wb = (i * DIM_ + c) * 9;
#pragma unroll
        for (int k = 0; k < 9; k++) wgt[i][k] = dw_w[wb + k];
        const float s = bn_g[i * DIM_ + c] * rsqrtf(bn_v[i * DIM_ + c] + 1e-5f);
        sc[i] = s;
        bi[i] = (dw_b[i * DIM_ + c] - bn_m[i * DIM_ + c]) * s + bn_b[i * DIM_ + c];
    }

    const float* xb = x + (long)b * N_ * DIM_ + c;
    const bool rv[3]  = { l - 1 >= 0, true, l + 1 < IMG_ };
    const int  rof[3] = { (l - 1) * IMG_, l * IMG_, (l + 1) * IMG_ };

    float c0[3], c1[3], c2[3];
#pragma unroll
    for (int r = 0; r < 3; r++) {
        c0[r] = 0.f;
        c1[r] = rv[r] ? xb[(long)(rof[r]) * DIM_] : 0.f;
    }

    for (int w = 0; w < IMG_; w++) {
#pragma unroll
        for (int r = 0; r < 3; r++)
            c2[r] = (rv[r] && (w + 1) < IMG_) ? xb[(long)(rof[r] + w + 1) * DIM_] : 0.f;

        const long oidx = ((long)b * N_ + l * IMG_ + w) * DIM_ + c;
#pragma unroll
        for (int i = 0; i < 3; i++) {
            float a =
                c0[0]*wgt[i][0] + c1[0]*wgt[i][1] + c2[0]*wgt[i][2] +
                c0[1]*wgt[i][3] + c1[1]*wgt[i][4] + c2[1]*wgt[i][5] +
                c0[2]*wgt[i][6] + c1[2]*wgt[i][7] + c2[2]*wgt[i][8];
            g_y[(long)i * PROJ + oidx] = __float2half_rn(a * sc[i] + bi[i]);
        }
#pragma unroll
        for (int r = 0; r < 3; r++) { c0[r] = c1[r]; c1[r] = c2[r]; }
    }
}

// ---------------------------------------------------------------------------
// Kernel 2/4: fp16 NT GEMM via HMMA, K-chunk 64, 2-stage cp.async
// (fill-after-compute). Block 128x128, 256 threads = 8 warps (4x2),
// warp tile 32x64. K-step order identical to verified round-13 kernel
// (sequential k16 steps 0..511) => bit-identical accumulation.
// Dynamic smem: 2 stages x (A 128x72 + B 128x72) halfs = 73728 B.
// ---------------------------------------------------------------------------
#define GEMM_SMEM 73728
#define GAS(s, r, c) smd[(s) * 18432 + (r) * 72 + (c)]
#define GBS(s, r, c) smd[(s) * 18432 + 9216 + (r) * 72 + (c)]

template <bool HALF_OUT>
__global__ void __launch_bounds__(256, 2) gemm_h_kernel(
    const __half* __restrict__ Ag, const __half* __restrict__ Wg,
    const float* __restrict__ biasg, void* __restrict__ Cg,
    long sA, long sW, long sBias, long sC)
{
    extern __shared__ __half smd[];

    const int z = blockIdx.z;
    const __half* A    = Ag + (long)z * sA;
    const __half* W    = Wg + (long)z * sW;
    const float*  bias = biasg + (long)z * sBias;

    const int tid  = threadIdx.x;
    const int lane = tid & 31;
    const int warp = tid >> 5;
    const int wm   = warp >> 1;
    const int wn   = warp & 1;
    const int bm   = blockIdx.y * 128;
    const int bn   = blockIdx.x * 128;

    float acc[2][8][4];
#pragma unroll
    for (int mt = 0; mt < 2; mt++)
#pragma unroll
        for (int nt = 0; nt < 8; nt++)
#pragma unroll
            for (int j = 0; j < 4; j++) acc[mt][nt][j] = 0.f;

    // prologue: fill chunks 0,1 into stages 0,1 (128x64 halfs per tile,
    // 1024 16B-units per tile, 4 per thread)
#pragma unroll
    for (int p = 0; p < 2; p++) {
#pragma unroll
        for (int u = 0; u < 4; u++) {
            const int idx = tid + 256 * u;      // 0..1023
            const int row = idx >> 3;           // 0..127
            const int c16 = idx & 7;            // 16B unit -> 8 halfs
            cp16(smem_u32(&GAS(p, row, c16 * 8)),
                 A + (long)(bm + row) * 512 + p * 64 + c16 * 8);
            cp16(smem_u32(&GBS(p, row, c16 * 8)),
                 W + (long)(bn + row) * 512 + p * 64 + c16 * 8);
        }
        CP_COMMIT();
    }

    const int aRow    = (lane & 15);
    const int aColSel = (lane >> 4) * 8;
    const int bRow    = (lane & 7) + (lane >> 4) * 8;
    const int bColSel = ((lane >> 3) & 1) * 8;

#pragma unroll 1
    for (int it = 0; it < 8; it++) {
        const int s = it & 1;
        if (it < 7) CP_WAIT1(); else CP_WAIT0();
        __syncthreads();                        // chunk it visible in stage s

#pragma unroll
        for (int ks = 0; ks < 4; ks++) {
            const int kk = ks * 16;
            unsigned af[2][4];
#pragma unroll
            for (int mt = 0; mt < 2; mt++) {
                unsigned addr = smem_u32(&GAS(s, wm * 32 + mt * 16 + aRow, kk + aColSel));
                ldm4(af[mt][0], af[mt][1], af[mt][2], af[mt][3], addr);
            }
            unsigned bf[8][2];
#pragma unroll
            for (int np = 0; np < 4; np++) {
                unsigned addr = smem_u32(&GBS(s, wn * 64 + np * 16 + bRow, kk + bColSel));
                unsigned r0, r1, r2, r3;
                ldm4(r0, r1, r2, r3, addr);
                bf[np * 2][0] = r0;     bf[np * 2][1] = r1;
                bf[np * 2 + 1][0] = r2; bf[np * 2 + 1][1] = r3;
            }
#pragma unroll
            for (int mt = 0; mt < 2; mt++)
#pragma unroll
                for (int nt = 0; nt < 8; nt++)
                    mma16816(acc[mt][nt], af[mt], bf[nt]);
        }

        __syncthreads();                        // all warps done reading stage s
        if (it + 2 < 8) {                       // refill stage s with chunk it+2
            const int ck = it + 2;
#pragma unroll
            for (int u = 0; u < 4; u++) {
                const int idx = tid + 256 * u;
                const int row = idx >> 3;
                const int c16 = idx & 7;
                cp16(smem_u32(&GAS(s, row, c16 * 8)),
                     A + (long)(bm + row) * 512 + ck * 64 + c16 * 8);
                cp16(smem_u32(&GBS(s, row, c16 * 8)),
                     W + (long)(bn + row) * 512 + ck * 64 + c16 * 8);
            }
            CP_COMMIT();
        }
    }

    const int rq = lane >> 2;
    const int cq = (lane & 3) * 2;
#pragma unroll
    for (int mt = 0; mt < 2; mt++) {
        const int row0 = bm + wm * 32 + mt * 16 + rq;
#pragma unroll
        for (int nt = 0; nt < 8; nt++) {
            const int col = bn + wn * 64 + nt * 8 + cq;
            const float b0 = bias[col], b1 = bias[col + 1];
            if (HALF_OUT) {
                __half* C = (__half*)Cg + (long)z * sC;
                *(__half2*)(C + (long)row0 * 512 + col) =
                    __floats2half2_rn(acc[mt][nt][0] + b0, acc[mt][nt][1] + b1);
                *(__half2*)(C + (long)(row0 + 8) * 512 + col) =
                    __floats2half2_rn(acc[mt][nt][2] + b0, acc[mt][nt][3] + b1);
            } else {
                float* C = (float*)Cg + (long)z * sC;
                *(float2*)(C + (long)row0 * 512 + col) =
                    make_float2(acc[mt][nt][0] + b0, acc[mt][nt][1] + b1);
                *(float2*)(C + (long)(row0 + 8) * 512 + col) =
                    make_float2(acc[mt][nt][2] + b0, acc[mt][nt][3] + b1);
            }
        }
    }
}

// ---------------------------------------------------------------------------
// Kernel 3: flash attention (round-13 verified: 57.1us).
// Max-free softmax, fp16x2 exp2, MMA row-sums, key-chunk structure,
// 3-stage cp.async K/V, 256 threads = 8 warps x m16.
// Dynamic smem: Q 128x72 + 3 stages x (K 64x72 + V 64x72) = 73728 B.
// ---------------------------------------------------------------------------
#define ATT_SMEM 73728
#define QS(r, c)     sm[(r) * 72 + (c)]
#define KS(s, r, c)  sm[9216  + (s) * 4608 + (r) * 72 + (c)]
#define VS(s, r, c)  sm[23040 + (s) * 4608 + (r) * 72 + (c)]

__global__ void __launch_bounds__(256, 2) attn_h_kernel(
    const __half* __restrict__ qkv, __half* __restrict__ attout)
{
    extern __shared__ __half sm[];

    const int tid  = threadIdx.x;
    const int lane = tid & 31;
    const int warp = tid >> 5;           // 0..7
    const int qt = blockIdx.x, h = blockIdx.y, b = blockIdx.z;

    const __half* Qg = qkv +            ((long)b * N_ + qt * 128) * 512 + h * 64;
    const __half* Kg = qkv + PROJ     + (long)b * N_ * 512 + h * 64;
    const __half* Vg = qkv + 2 * PROJ + (long)b * N_ * 512 + h * 64;

#pragma unroll
    for (int p = 0; p < 2; p++) {
#pragma unroll
        for (int c = 0; c < 2; c++) {
            const int idx = tid + 256 * c;
            const int row = idx >> 3;
            const int col = (idx & 7) * 8;
            cp16(smem_u32(&KS(p, row, col)), Kg + (long)(p * 64 + row) * 512 + col);
            cp16(smem_u32(&VS(p, row, col)), Vg + (long)(p * 64 + row) * 512 + col);
        }
        CP_COMMIT();
    }

    {
        const __half2 s2 = __float2half2_rn(0.125f * 1.4426950408889634f);
#pragma unroll
        for (int p = 0; p < 4; p++) {
            const int idx = tid + 256 * p;
            const int r   = idx >> 3;
            const int col = (idx & 7) * 8;
            uint4 v = *(const uint4*)(Qg + (long)r * 512 + col);
            __half2* hv = (__half2*)&v;
#pragma unroll
            for (int i = 0; i < 4; i++) hv[i] = __hmul2(hv[i], s2);
            *(uint4*)&QS(r, col) = v;
        }
    }
    __syncthreads();

    unsigned qf[4][4];
    {
        const int r = warp * 16 + (lane >> 2);
#pragma unroll
        for (int ks = 0; ks < 4; ks++) {
            const int d = ks * 16 + (lane & 3) * 2;
            qf[ks][0] = *(const unsigned*)&QS(r, d);
            qf[ks][1] = *(const unsigned*)&QS(r + 8, d);
            qf[ks][2] = *(const unsigned*)&QS(r, d + 8);
            qf[ks][3] = *(const unsigned*)&QS(r + 8, d + 8);
        }
    }

    float o[8][4];
#pragma unroll
    for (int nt = 0; nt < 8; nt++)
#pragma unroll
        for (int j = 0; j < 4; j++) o[nt][j] = 0.f;
    float rs[4] = {0.f, 0.f, 0.f, 0.f};
    const unsigned ONES2 = 0x3C003C00u;
    const unsigned bones[2] = { ONES2, ONES2 };

    const int bRow = (lane & 7) + (lane >> 4) * 8;
    const int bColSel = ((lane >> 3) & 1) * 8;
    const int vRow = ((lane >> 3) & 1) * 8 + (lane & 7);
    const int vCol = (lane >> 4) * 8;

    for (int kt = 0; kt < 16; kt++) {
        const int s = kt % 3;
        if (kt < 15) CP_WAIT1(); else CP_WAIT0();
        __syncthreads();
        if (kt + 2 < 16) {
            const int nk = kt + 2, ns = nk % 3;
#pragma unroll
            for (int c = 0; c < 2; c++) {
                const int idx = tid + 256 * c;
                const int row = idx >> 3;
                const int col = (idx & 7) * 8;
                cp16(smem_u32(&KS(ns, row, col)),
                     Kg + (long)(nk * 64 + row) * 512 + col);
                cp16(smem_u32(&VS(ns, row, col)),
                     Vg + (long)(nk * 64 + row) * 512 + col);
            }
            CP_COMMIT();
        }

#pragma unroll
        for (int t = 0; t < 4; t++) {
            float s0[4] = {0.f, 0.f, 0.f, 0.f};
            float s1[4] = {0.f, 0.f, 0.f, 0.f};
#pragma unroll
            for (int ks = 0; ks < 4; ks++) {
                unsigned r0, r1, r2, r3;
                ldm4(r0, r1, r2, r3,
                     smem_u32(&KS(s, t * 16 + bRow, ks * 16 + bColSel)));
                unsigned kb0[2] = { r0, r1 };
                unsigned kb1[2] = { r2, r3 };
                mma16816(s0, qf[ks], kb0);
                mma16816(s1, qf[ks], kb1);
            }

            unsigned pa[4];
            pa[0] = hex2(pack_h2(s0[0], s0[1]));
            pa[1] = hex2(pack_h2(s0[2], s0[3]));
            pa[2] = hex2(pack_h2(s1[0], s1[1]));
            pa[3] = hex2(pack_h2(s1[2], s1[3]));

            mma16816(rs, pa, bones);

#pragma unroll
            for (int dg = 0; dg < 4; dg++) {
                unsigned r0, r1, r2, r3;
                ldm4t(r0, r1, r2, r3,
                      smem_u32(&VS(s, t * 16 + vRow, dg * 16 + vCol)));
                unsigned bf0[2] = { r0, r1 };
                unsigned bf1[2] = { r2, r3 };
                mma16816(o[dg * 2],     pa, bf0);
                mma16816(o[dg * 2 + 1], pa, bf1);
            }
        }
    }

    const float inva = 1.f / rs[0], invb = 1.f / rs[2];
    const int r = warp * 16 + (lane >> 2);
    const long row0 = (long)b * N_ + qt * 128 + r;
#pragma unroll
    for (int nt = 0; nt < 8; nt++) {
        const int col = h * 64 + nt * 8 + (lane & 3) * 2;
        *(__half2*)(attout + row0 * 512 + col) =
            __floats2half2_rn(o[nt][0] * inva, o[nt][1] * inva);
        *(__half2*)(attout + (row0 + 8) * 512 + col) =
            __floats2half2_rn(o[nt][2] * invb, o[nt][3] * invb);
    }
}

// ---------------------------------------------------------------------------
// Host launcher (graph-capturable: kernel launches only)
// ---------------------------------------------------------------------------
extern "C" void kernel_launch(void* const* d_in, const int* in_sizes, int n_in,
                              void* d_out, int out_size)
{
    const float* x     = (const float*)d_in[0];
    const float* dw_w  = (const float*)d_in[1];
    const float* dw_b  = (const float*)d_in[2];
    const float* bn_g  = (const float*)d_in[3];
    const float* bn_b  = (const float*)d_in[4];
    const float* bn_m  = (const float*)d_in[5];
    const float* bn_v  = (const float*)d_in[6];
    const float* pw_w  = (const float*)d_in[7];
    const float* pw_b  = (const float*)d_in[8];
    const float* out_w = (const float*)d_in[9];
    const float* out_b = (const float*)d_in[10];

    __half *yp, *qkvp, *attp, *pwp, *owp;
    cudaGetSymbolAddress((void**)&yp,   g_y);
    cudaGetSymbolAddress((void**)&qkvp, g_qkv);
    cudaGetSymbolAddress((void**)&attp, g_att);
    cudaGetSymbolAddress((void**)&pwp,  g_pw);
    cudaGetSymbolAddress((void**)&owp,  g_ow);

    cudaFuncSetAttribute(attn_h_kernel,
                         cudaFuncAttributeMaxDynamicSharedMemorySize, ATT_SMEM);
    cudaFuncSetAttribute(gemm_h_kernel<true>,
                         cudaFuncAttributeMaxDynamicSharedMemorySize, GEMM_SMEM);
    cudaFuncSetAttribute(gemm_h_kernel<false>,
                         cudaFuncAttributeMaxDynamicSharedMemorySize, GEMM_SMEM);

    // 1) depthwise + BN (fp16 out) with fused weight conversion (grid.z=2)
    dwconv_bn_kernel<<<dim3(IMG_, B_, 2), DIM_>>>(x, dw_w, dw_b,
                                                  bn_g, bn_b, bn_m, bn_v,
                                                  pw_w, out_w);

    // 2) pointwise 1x1 conv: 3 fp16 GEMMs (K-chunk 64)
    gemm_h_kernel<true><<<dim3(4, 64, 3), 256, GEMM_SMEM>>>(
        yp, pwp, pw_b, (void*)qkvp,
        PROJ, (long)INNER_ * DIM_, (long)INNER_, PROJ);

    // 3) fused flash attention (round-13 verified)
    attn_h_kernel<<<dim3(N_ / 128, HEADS_, B_), 256, ATT_SMEM>>>(qkvp, attp);

    // 4) output projection -> d_out (fp32)
    gemm_h_kernel<false><<<dim3(4, 64, 1), 256, GEMM_SMEM>>>(
        attp, owp, out_b, d_out, 0, 0, 0, 0);
}